// round 2
// baseline (speedup 1.0000x reference)
#include <cuda_runtime.h>

// TransOp expm: out[b, s*8..] = expm(A_{b,s}) @ x[b, s*8..]
// A_{b,s} = sum_m c[b,m] * psi[m,s,:,:]   (8x8)
// Method: scale A by 2^-s until ||A||_inf <= 1, then apply order-8 Taylor
// action 2^s times (exp(A)x = (exp(A/2^s))^{2^s} x). One thread per (b,s).

#define BDIM 256

__global__ __launch_bounds__(BDIM) void transop_expm_kernel(
    const float* __restrict__ x,
    const float* __restrict__ c,
    const float* __restrict__ psi,
    float* __restrict__ out)
{
    __shared__ float ps[16][64];   // psi[:, s, :, :] for this CTA's fixed s

    const int s = blockIdx.x & 63;
    const int b = (blockIdx.x >> 6) * BDIM + threadIdx.x;

    // Stage psi slice: 16*64 floats = 4KB, 256 threads x 1 float4 each.
    {
        const int t = threadIdx.x;
        const int m = t >> 4;          // 0..15
        const int j = (t & 15) << 2;   // 0,4,...,60
        const float4 v = *reinterpret_cast<const float4*>(psi + ((m * 64 + s) << 6) + j);
        *reinterpret_cast<float4*>(&ps[m][j]) = v;
    }
    __syncthreads();

    // Load c[b, 0..15]
    float cm[16];
    {
        const float4* cb = reinterpret_cast<const float4*>(c + b * 16);
        const float4 c0 = cb[0], c1 = cb[1], c2 = cb[2], c3 = cb[3];
        cm[0]=c0.x; cm[1]=c0.y; cm[2]=c0.z; cm[3]=c0.w;
        cm[4]=c1.x; cm[5]=c1.y; cm[6]=c1.z; cm[7]=c1.w;
        cm[8]=c2.x; cm[9]=c2.y; cm[10]=c2.z; cm[11]=c2.w;
        cm[12]=c3.x; cm[13]=c3.y; cm[14]=c3.z; cm[15]=c3.w;
    }

    // Build A (row-major 8x8) in registers: A[j] = sum_m cm[m]*ps[m][j]
    float A[64];
#pragma unroll
    for (int j = 0; j < 64; ++j) {
        float a = cm[0] * ps[0][j];
#pragma unroll
        for (int m = 1; m < 16; ++m) a = fmaf(cm[m], ps[m][j], a);
        A[j] = a;
    }

    // Infinity norm (max abs row sum)
    float ninf = 0.0f;
#pragma unroll
    for (int n = 0; n < 8; ++n) {
        float r = 0.0f;
#pragma unroll
        for (int k = 0; k < 8; ++k) r += fabsf(A[n * 8 + k]);
        ninf = fmaxf(ninf, r);
    }

    // Number of halvings so that ||A||_inf / 2^sc <= 1
    int sc = 0;
    float nm = ninf;
    while (nm > 1.0f && sc < 14) { nm *= 0.5f; ++sc; }
    const float scale = __int_as_float((127 - sc) << 23);  // 2^-sc exactly
#pragma unroll
    for (int j = 0; j < 64; ++j) A[j] *= scale;

    // Load x block
    float y[8];
    {
        const float4* xb = reinterpret_cast<const float4*>(x + b * 512 + s * 8);
        const float4 x0 = xb[0], x1 = xb[1];
        y[0]=x0.x; y[1]=x0.y; y[2]=x0.z; y[3]=x0.w;
        y[4]=x1.x; y[5]=x1.y; y[6]=x1.z; y[7]=x1.w;
    }

    // Repeated Taylor action: y <- (I + A + A^2/2! + ... + A^8/8!) y, 2^sc times
    const int reps = 1 << sc;
    for (int r = 0; r < reps; ++r) {
        float v[8], acc[8];
#pragma unroll
        for (int n = 0; n < 8; ++n) { v[n] = y[n]; acc[n] = y[n]; }
#pragma unroll
        for (int j = 1; j <= 8; ++j) {
            float w[8];
#pragma unroll
            for (int n = 0; n < 8; ++n) {
                float t0 = A[n * 8 + 0] * v[0];
#pragma unroll
                for (int k = 1; k < 8; ++k) t0 = fmaf(A[n * 8 + k], v[k], t0);
                w[n] = t0;
            }
            const float inv = 1.0f / (float)j;   // compile-time constant (unrolled)
#pragma unroll
            for (int n = 0; n < 8; ++n) { v[n] = w[n] * inv; acc[n] += v[n]; }
        }
#pragma unroll
        for (int n = 0; n < 8; ++n) y[n] = acc[n];
    }

    // Store result
    {
        float4* ob = reinterpret_cast<float4*>(out + b * 512 + s * 8);
        ob[0] = make_float4(y[0], y[1], y[2], y[3]);
        ob[1] = make_float4(y[4], y[5], y[6], y[7]);
    }
}

extern "C" void kernel_launch(void* const* d_in, const int* in_sizes, int n_in,
                              void* d_out, int out_size)
{
    const float* x   = (const float*)d_in[0];   // (B, 512)
    const float* c   = (const float*)d_in[1];   // (B, 16)
    const float* psi = (const float*)d_in[2];   // (16, 64, 8, 8)
    float* out = (float*)d_out;                 // (B, 512)

    const int B = in_sizes[0] / 512;            // 8192
    const dim3 grid((B / BDIM) * 64);           // 2048 CTAs, each: fixed s, 256 b's
    transop_expm_kernel<<<grid, BDIM>>>(x, c, psi, out);
}

// round 3
// speedup vs baseline: 1.5103x; 1.5103x over previous
#include <cuda_runtime.h>

// TransOp expm: out[b, s*8..] = expm(A_{b,s}) @ x[b, s*8..]
// A_{b,s} = sum_m c[b,m] * psi[m,s,:,:]   (8x8), one thread per (b,s).
//
// Method: Taylor-action (Al-Mohy/Higham style). Warp-uniform (order m, reps r)
// chosen from warp-max ||A||_inf:
//   wmax <= 3.2 : m=16, r=1   (err ~ 3.2^17/17! ~ 1.1e-6)
//   wmax <= 6.0 : m=24, r=1   (err ~ 6^25/25!   ~ 1.8e-6)
//   else        : m=16, r=ceil(wmax/3.2)
// Horner: v = b; for j=m..1: v = b + (A v)/j; repeated r times on A/r.
//
// All heavy FP uses packed f32x2 (FFMA2): A held as 32 x 64-bit regs, each
// packing the same column k of adjacent rows {2n2, 2n2+1}. psi is staged in
// shared memory already in this row-paired layout so the packed A-build reads
// 64-bit smem words directly.

typedef unsigned long long ull;

#define BDIM 256

__constant__ float INV_TAB[32] = {
    0.0f,      1.0f,      1.0f/2,    1.0f/3,    1.0f/4,    1.0f/5,
    1.0f/6,    1.0f/7,    1.0f/8,    1.0f/9,    1.0f/10,   1.0f/11,
    1.0f/12,   1.0f/13,   1.0f/14,   1.0f/15,   1.0f/16,   1.0f/17,
    1.0f/18,   1.0f/19,   1.0f/20,   1.0f/21,   1.0f/22,   1.0f/23,
    1.0f/24,   1.0f/25,   1.0f/26,   1.0f/27,   1.0f/28,   1.0f/29,
    1.0f/30,   1.0f/31
};

__device__ __forceinline__ ull dup2(float v) {
    ull r; asm("mov.b64 %0, {%1,%1};" : "=l"(r) : "f"(v)); return r;
}
__device__ __forceinline__ void unpack2(ull v, float& lo, float& hi) {
    asm("mov.b64 {%0,%1}, %2;" : "=f"(lo), "=f"(hi) : "l"(v));
}
__device__ __forceinline__ ull fma2(ull a, ull b, ull c) {
    ull d; asm("fma.rn.f32x2 %0, %1, %2, %3;" : "=l"(d) : "l"(a), "l"(b), "l"(c)); return d;
}
__device__ __forceinline__ ull mul2(ull a, ull b) {
    ull d; asm("mul.rn.f32x2 %0, %1, %2;" : "=l"(d) : "l"(a), "l"(b)); return d;
}
__device__ __forceinline__ ull add2(ull a, ull b) {
    ull d; asm("add.rn.f32x2 %0, %1, %2;" : "=l"(d) : "l"(a), "l"(b)); return d;
}

__global__ __launch_bounds__(BDIM) void transop_expm_kernel(
    const float* __restrict__ x,
    const float* __restrict__ c,
    const float* __restrict__ psi,
    float* __restrict__ out)
{
    // psi slice for this CTA's s, row-paired packed:
    // ps2[m][n2*8+k] = { psi[m,s,2*n2,k], psi[m,s,2*n2+1,k] }
    __shared__ ull ps2[16][32];

    const int s = blockIdx.x & 63;
    const int b = (blockIdx.x >> 6) * BDIM + threadIdx.x;

    // Stage psi: 256 threads x one float4 each (1024 floats total).
    {
        const int t = threadIdx.x;
        const int m = t >> 4;            // 0..15
        const int j = (t & 15) << 2;     // 0,4,...,60 : linear n*8+k
        const float4 v = *reinterpret_cast<const float4*>(psi + ((m * 64 + s) << 6) + j);
        const int n = j >> 3;            // row 0..7
        const int k0 = j & 7;            // 0 or 4
        float* dst = reinterpret_cast<float*>(&ps2[m][(n >> 1) * 8 + k0]);
        const int w = n & 1;             // lo/hi half of the pair
        dst[0 * 2 + w] = v.x;
        dst[1 * 2 + w] = v.y;
        dst[2 * 2 + w] = v.z;
        dst[3 * 2 + w] = v.w;
    }
    __syncthreads();

    // c[b, 0..15], duplicated into packed form.
    ull cm2[16];
    {
        const float4* cb = reinterpret_cast<const float4*>(c + b * 16);
#pragma unroll
        for (int q = 0; q < 4; ++q) {
            const float4 cv = cb[q];
            cm2[q * 4 + 0] = dup2(cv.x);
            cm2[q * 4 + 1] = dup2(cv.y);
            cm2[q * 4 + 2] = dup2(cv.z);
            cm2[q * 4 + 3] = dup2(cv.w);
        }
    }

    // Packed A build: A2[n2*8+k] = { A[2n2][k], A[2n2+1][k] }
    ull A2[32];
#pragma unroll
    for (int i = 0; i < 32; ++i) A2[i] = mul2(cm2[0], ps2[0][i]);
#pragma unroll
    for (int m = 1; m < 16; ++m) {
#pragma unroll
        for (int i = 0; i < 32; ++i) A2[i] = fma2(cm2[m], ps2[m][i], A2[i]);
    }

    // Infinity norm: packed abs-rowsum gives both rows of a pair at once.
    float ninf = 0.0f;
    {
        const ull mask = 0x7FFFFFFF7FFFFFFFULL;
#pragma unroll
        for (int n2 = 0; n2 < 4; ++n2) {
            ull acc = A2[n2 * 8] & mask;
#pragma unroll
            for (int k = 1; k < 8; ++k) acc = add2(acc, A2[n2 * 8 + k] & mask);
            float r0, r1; unpack2(acc, r0, r1);
            ninf = fmaxf(ninf, fmaxf(r0, r1));
        }
    }

    // Warp-uniform (order, reps) selection from warp-max norm.
    const float wmax = __uint_as_float(
        __reduce_max_sync(0xffffffffu, __float_as_uint(ninf)));

    int m_ord, r;
    if (wmax <= 3.2f)       { m_ord = 16; r = 1; }
    else if (wmax <= 6.0f)  { m_ord = 24; r = 1; }
    else {
        r = (int)ceilf(wmax * (1.0f / 3.2f));
        if (r > 31) r = 31;
        m_ord = 16;
    }

    // Scale A by 1/r (exact 1.0 when r==1).
    {
        const ull s2 = dup2(INV_TAB[r] + (r == 1 ? 0.0f : 0.0f));
#pragma unroll
        for (int i = 0; i < 32; ++i) A2[i] = mul2(A2[i], s2);
    }

    // Load x block (pairs are naturally adjacent floats).
    ull v2[4];
    {
        const ull* xb = reinterpret_cast<const ull*>(x + b * 512 + s * 8);
        v2[0] = xb[0]; v2[1] = xb[1]; v2[2] = xb[2]; v2[3] = xb[3];
    }

    // r repetitions of order-m Horner Taylor action.
    for (int rr = 0; rr < r; ++rr) {
        ull b2[4];
#pragma unroll
        for (int i = 0; i < 4; ++i) b2[i] = v2[i];

        for (int j = m_ord; j > 0; --j) {
            float vf[8];
            unpack2(v2[0], vf[0], vf[1]);
            unpack2(v2[1], vf[2], vf[3]);
            unpack2(v2[2], vf[4], vf[5]);
            unpack2(v2[3], vf[6], vf[7]);
            ull d[8];
#pragma unroll
            for (int k = 0; k < 8; ++k) d[k] = dup2(vf[k]);

            ull w2[4];
#pragma unroll
            for (int n2 = 0; n2 < 4; ++n2) {
                ull acc = mul2(A2[n2 * 8], d[0]);
#pragma unroll
                for (int k = 1; k < 8; ++k) acc = fma2(A2[n2 * 8 + k], d[k], acc);
                w2[n2] = acc;
            }

            const ull s2 = dup2(INV_TAB[j]);
#pragma unroll
            for (int n2 = 0; n2 < 4; ++n2) v2[n2] = fma2(w2[n2], s2, b2[n2]);
        }
    }

    // Store (packed pairs are already in output element order).
    {
        ull* ob = reinterpret_cast<ull*>(out + b * 512 + s * 8);
        ob[0] = v2[0]; ob[1] = v2[1]; ob[2] = v2[2]; ob[3] = v2[3];
    }
}

extern "C" void kernel_launch(void* const* d_in, const int* in_sizes, int n_in,
                              void* d_out, int out_size)
{
    const float* x   = (const float*)d_in[0];   // (B, 512)
    const float* c   = (const float*)d_in[1];   // (B, 16)
    const float* psi = (const float*)d_in[2];   // (16, 64, 8, 8)
    float* out = (float*)d_out;                 // (B, 512)

    const int B = in_sizes[0] / 512;            // 8192
    const dim3 grid((B / BDIM) * 64);           // 2048 CTAs: fixed s, 256 b's each
    transop_expm_kernel<<<grid, BDIM>>>(x, c, psi, out);
}